// round 15
// baseline (speedup 1.0000x reference)
#include <cuda_runtime.h>

#define BB 4
#define PP 2048
#define EE 1024
#define HH 16
#define HD 64
#define NB2 64          // ks bins
#define NC 11           // Taylor coefs c0..c10
#define NPART 8
#define NVP 32
#define NNODE 512       // interpolation nodes per bh

// Scratch (fully overwritten every launch)
__device__ __align__(16) float g_Qs[BB*HH*PP];
__device__ __align__(16) float g_Ks[BB*HH*PP];
__device__ __align__(16) float g_Vpart[BB*NVP*EE];
__device__ __align__(16) float g_U[BB*HH*EE];       // [b][h][n]
__device__ __align__(16) float g_diag[BB*HH*PP];
__device__ __align__(16) float g_bt[BB*HH*NPART*NC*NB2];
__device__ __align__(16) float g_tab[BB*HH*NNODE];  // log2-denominator nodes
__device__ __align__(8)  float2 g_mnmx[BB*HH];      // ks min/max
__device__ __align__(16) float4 g_qmm[BB*HH];       // (amin2, h2, 1/h2, pad)

__device__ __forceinline__ float ex2f(float x){
    float y; asm("ex2.approx.ftz.f32 %0, %1;" : "=f"(y) : "f"(x)); return y;
}
__device__ __forceinline__ float lg2f(float x){
    float y; asm("lg2.approx.f32 %0, %1;" : "=f"(y) : "f"(x)); return y;
}

// ---------------------------------------------------------------------------
// K1: blocks [0,512): V partial column sums. [512,8704): Q/K head row-sums.
// ---------------------------------------------------------------------------
__global__ void k_reduce(const float* __restrict__ Q, const float* __restrict__ K,
                         const float* __restrict__ V) {
    int bid = blockIdx.x;
    int tid = threadIdx.x;
    if (bid < 512) {
        int b = bid >> 7, r = bid & 127, pc = r >> 2, cg = r & 3;
        int c = cg * 256 + tid;
        const float* base = V + ((size_t)b * PP + pc * 64) * EE + c;
        float s = 0.f;
        #pragma unroll 16
        for (int p = 0; p < 64; p++) s += base[(size_t)p * EE];
        g_Vpart[(b * NVP + pc) * EE + c] = s;
    } else {
        int base = bid - 512;
        const float* src; float* dst;
        if (base < 4096) { src = Q; dst = g_Qs; }
        else             { src = K; dst = g_Ks; base -= 4096; }
        int bh = base >> 6;
        int ptile = base & 63;
        int b = bh >> 4, h = bh & 15;
        int seg = tid >> 4, lane16 = tid & 15;
        int p0 = ptile * 32 + seg;
        const float4* r0 = (const float4*)(src + (((size_t)(b * PP + p0)) << 10) + h * HD);
        const float4* r1 = (const float4*)(src + (((size_t)(b * PP + p0 + 16)) << 10) + h * HD);
        float4 v0 = r0[lane16];
        float4 v1 = r1[lane16];
        float s0 = (v0.x + v0.y) + (v0.z + v0.w);
        float s1 = (v1.x + v1.y) + (v1.z + v1.w);
        #pragma unroll
        for (int off = 8; off; off >>= 1) {
            s0 += __shfl_down_sync(0xffffffffu, s0, off, 16);
            s1 += __shfl_down_sync(0xffffffffu, s1, off, 16);
        }
        __shared__ float sm[32];
        if (lane16 == 0) { sm[seg] = s0; sm[16 + seg] = s1; }
        __syncthreads();
        if (tid < 32) dst[(bh << 11) + ptile * 32 + tid] = sm[tid];
    }
}

// ---------------------------------------------------------------------------
// min/max of arr[2048], exact. 256 threads.
// ---------------------------------------------------------------------------
__device__ __forceinline__ void ks_minmax(const float4* kr4, int tid,
                                          float* s_mn, float* s_mx) {
    __shared__ float rmn[8], rmx[8];
    float mn = 3.4e38f, mx = -3.4e38f;
    #pragma unroll
    for (int i = 0; i < 2; i++) {
        float4 v = kr4[i * 256 + tid];
        mn = fminf(mn, fminf(fminf(v.x, v.y), fminf(v.z, v.w)));
        mx = fmaxf(mx, fmaxf(fmaxf(v.x, v.y), fmaxf(v.z, v.w)));
    }
    #pragma unroll
    for (int off = 16; off; off >>= 1) {
        mn = fminf(mn, __shfl_xor_sync(0xffffffffu, mn, off));
        mx = fmaxf(mx, __shfl_xor_sync(0xffffffffu, mx, off));
    }
    if ((tid & 31) == 0) { rmn[tid >> 5] = mn; rmx[tid >> 5] = mx; }
    __syncthreads();
    if (tid == 0) {
        float a = rmn[0], c = rmx[0];
        #pragma unroll
        for (int w = 1; w < 8; w++) { a = fminf(a, rmn[w]); c = fmaxf(c, rmx[w]); }
        *s_mn = a; *s_mx = c;
    }
    __syncthreads();
}

// ---------------------------------------------------------------------------
// K_mid: [0,512): ks bin tables. [512,768): proj_u. [768,832): Qs min/max.
// ---------------------------------------------------------------------------
__global__ void k_mid(const float* __restrict__ W) {
    int bid = blockIdx.x;
    int tid = threadIdx.x;
    if (bid < 512) {
        int bh = bid >> 3, part = bid & 7;
        __shared__ float s_mn, s_mx;
        __shared__ float tb[NC][NB2];
        const float4* kr4 = (const float4*)(g_Ks + ((size_t)bh << 11));
        ks_minmax(kr4, tid, &s_mn, &s_mx);
        for (int i = tid; i < NC * NB2; i += 256) ((float*)tb)[i] = 0.f;
        __syncthreads();

        float mn = s_mn, mx = s_mx;
        float w = fmaxf(mx - mn, 1e-20f) * (1.0f / NB2);
        float invw = 1.0f / w;

        float k = g_Ks[((size_t)bh << 11) + (part << 8) + tid];
        int idx = (int)((k - mn) * invw);
        idx = max(0, min(NB2 - 1, idx));
        float kb = mn + ((float)idx + 0.5f) * w;
        float d  = k - kb;
        float t = 1.0f;
        atomicAdd(&tb[0][idx], 1.0f);
        const float rc[10] = {1.f, 0.5f, 1.f/3.f, 0.25f, 0.2f, 1.f/6.f,
                              1.f/7.f, 0.125f, 1.f/9.f, 0.1f};
        #pragma unroll
        for (int c = 1; c <= 10; c++) {
            t *= d * rc[c - 1];
            atomicAdd(&tb[c][idx], t);
        }
        __syncthreads();

        float* out = g_bt + (size_t)((bh * NPART + part) * NC) * NB2;
        for (int i = tid; i < NC * NB2; i += 256) out[i] = ((float*)tb)[i];
        if (part == 0 && tid == 0) g_mnmx[bh] = make_float2(mn, mx);
    } else if (bid < 768) {
        int blk = bid - 512;
        int b = blk >> 6, h = (blk >> 2) & 15, nc = blk & 3;
        __shared__ float vs[HD];
        if (tid < HD) {
            float s = 0.f;
            #pragma unroll
            for (int pc = 0; pc < NVP; pc++)
                s += g_Vpart[(b * NVP + pc) * EE + h * HD + tid];
            vs[tid] = s;
        }
        __syncthreads();
        int n = nc * 256 + tid;
        const float4* wr = (const float4*)(W + (size_t)n * EE + h * HD);
        float acc = 0.f;
        #pragma unroll
        for (int e = 0; e < 16; e++) {
            float4 w4 = wr[e];
            acc += w4.x * vs[4*e] + w4.y * vs[4*e+1] + w4.z * vs[4*e+2] + w4.w * vs[4*e+3];
        }
        g_U[((b * HH + h) << 10) + n] = acc;
    } else {
        int bh = bid - 768;
        __shared__ float s_mn, s_mx;
        ks_minmax((const float4*)(g_Qs + ((size_t)bh << 11)), tid, &s_mn, &s_mx);
        if (tid == 0) {
            const float C2 = 0.125f * 1.44269504088896340736f;
            float amin2 = C2 * s_mn, amax2 = C2 * s_mx;
            if (amin2 > amax2) { float t2 = amin2; amin2 = amax2; amax2 = t2; }
            float h2 = fmaxf(amax2 - amin2, 1e-20f) * (1.0f / 507.0f);
            g_qmm[bh] = make_float4(amin2, h2, 1.0f / h2, 0.f);
        }
    }
}

// ---------------------------------------------------------------------------
// K_nodes: g(a2) = log2 sum_j 2^(a2*ks_j) at 512 nodes per bh.
//   grid 128 = 64bh x 2 halves; 256 threads = 1 node each.
// ---------------------------------------------------------------------------
__global__ void __launch_bounds__(256) k_nodes() {
    int bh = blockIdx.x >> 1, half = blockIdx.x & 1;
    int tid = threadIdx.x;
    __shared__ __align__(16) float cf[NB2][12];
    __shared__ float2 s_mm;
    __shared__ float4 s_qmm;
    if (tid == 0) { s_mm = g_mnmx[bh]; s_qmm = g_qmm[bh]; }

    {
        const float* bt = g_bt + (size_t)(bh * NPART * NC) * NB2;
        for (int i = tid; i < NC * NB2; i += 256) {
            int c = i >> 6, bin = i & 63;
            float s = 0.f;
            #pragma unroll
            for (int part = 0; part < NPART; part++)
                s += bt[(size_t)(part * NC) * NB2 + i];
            cf[bin][c] = s;
        }
        for (int i = tid; i < NB2; i += 256) cf[i][11] = 0.f;
    }
    __syncthreads();

    float mn = s_mm.x, mx = s_mm.y;
    float w = fmaxf(mx - mn, 1e-20f) * (1.0f / NB2);
    const float LN2 = 0.69314718055994530942f;

    int node = half * 256 + tid;
    float a2 = fmaf((float)(node - 2), s_qmm.y, s_qmm.x);
    float a  = a2 * LN2;
    float nM = -((a2 >= 0.f) ? a2 * mx : a2 * mn);
    float rd = ex2f(a2 * w);

    float acc0 = 0.f, acc1 = 0.f;
    #pragma unroll 1
    for (int seg = 0; seg < 4; seg++) {
        float kb = fmaf((float)(seg * 16) + 0.5f, w, mn);
        float e  = ex2f(fmaf(a2, kb, nM));
        float accs = 0.f;
        #pragma unroll
        for (int t = 0; t < 16; t++) {
            int bin = seg * 16 + t;
            float4 A = *(const float4*)&cf[bin][0];
            float4 B = *(const float4*)&cf[bin][4];
            float4 C = *(const float4*)&cf[bin][8];
            float p = C.z;
            p = fmaf(a, p, C.y);
            p = fmaf(a, p, C.x);
            p = fmaf(a, p, B.w);
            p = fmaf(a, p, B.z);
            p = fmaf(a, p, B.y);
            p = fmaf(a, p, B.x);
            p = fmaf(a, p, A.w);
            p = fmaf(a, p, A.z);
            p = fmaf(a, p, A.y);
            p = fmaf(a, p, A.x);
            accs = fmaf(e, p, accs);
            e *= rd;
        }
        if (seg & 1) acc1 += accs; else acc0 += accs;
    }
    float denom = acc0 + acc1;
    g_tab[(bh << 9) + node] = lg2f(denom) - nM;
}

// ---------------------------------------------------------------------------
// K_diag: Catmull-Rom cubic on g_tab -> g(a2); diag = 2^(a2*ki - g).
//   grid 128 = 64bh x 2 chunks of 1024; thread handles 4 queries (ILP).
// ---------------------------------------------------------------------------
__global__ void __launch_bounds__(256) k_diag() {
    int bh = blockIdx.x >> 1, ch = blockIdx.x & 1;
    int tid = threadIdx.x;
    __shared__ __align__(16) float gt[NNODE];
    __shared__ float4 s_qmm;
    if (tid == 0) s_qmm = g_qmm[bh];
    if (tid < 128)
        ((float4*)gt)[tid] = ((const float4*)(g_tab + (bh << 9)))[tid];
    __syncthreads();

    const float C2 = 0.125f * 1.44269504088896340736f;
    float a2v[4], kiv[4];
    #pragma unroll
    for (int q = 0; q < 4; q++) {
        int i = (ch << 10) + q * 256 + tid;
        a2v[q] = C2 * g_Qs[((size_t)bh << 11) + i];
        kiv[q] = g_Ks[((size_t)bh << 11) + i];
    }
    #pragma unroll
    for (int q = 0; q < 4; q++) {
        int i = (ch << 10) + q * 256 + tid;
        float x = fmaf(a2v[q] - s_qmm.x, s_qmm.z, 2.0f);
        int i0 = (int)floorf(x);
        i0 = min(max(i0, 1), 509);
        float t = x - (float)i0;
        float g0 = gt[i0 - 1], g1 = gt[i0], g2 = gt[i0 + 1], g3 = gt[i0 + 2];
        float m1 = 0.5f * (g2 - g0);
        float m2 = 0.5f * (g3 - g1);
        float dg = g2 - g1;
        float c2v = 3.f * dg - 2.f * m1 - m2;
        float c3v = -2.f * dg + m1 + m2;
        float g = g1 + t * (m1 + t * (c2v + t * c3v));
        g_diag[((size_t)bh << 11) + i] = ex2f(fmaf(a2v[q], kiv[q], -g));
    }
}

// ---------------------------------------------------------------------------
// K4: Y[b,p,n] = sum_h diag[b,h,p]*U[b,h,n] + bias[n].
//   Thread = 4p x 16n (u in 64 regs); block = 16p x 1024n, 256 threads
//   (4 p-groups x 64 n-threads). Per thread: 64 LDS + 1024 FFMA + 16 STG
//   -> LDS:FFMA = 1:16. grid 512 = 4b x 128pt.
// ---------------------------------------------------------------------------
__global__ void __launch_bounds__(256) k_out(const float* __restrict__ bias,
                                             float* __restrict__ Y) {
    int pt = blockIdx.x & 127;    // 128 tiles of 16 p
    int b  = blockIdx.x >> 7;
    int tid = threadIdx.x;
    __shared__ float dsm[HH * 16];
    // load diag tile: 16h x 16p = 256 floats (1 per thread)
    {
        int h = tid >> 4, pl = tid & 15;
        dsm[h * 16 + pl] = g_diag[(((size_t)(b * HH + h)) << 11) + pt * 16 + pl];
    }
    __syncthreads();

    int pg = tid >> 6;            // p-group of 4 (0..3)
    int nx = tid & 63;            // n-thread (16 n each)
    int n0 = nx << 4;

    // u[h][0..3]: 16h x 16n in 64 registers
    float4 u[HH][4];
    #pragma unroll
    for (int h = 0; h < HH; h++) {
        const float4* up = (const float4*)(g_U + ((b * HH + h) << 10) + n0);
        u[h][0] = up[0]; u[h][1] = up[1]; u[h][2] = up[2]; u[h][3] = up[3];
    }
    float4 bn[4];
    #pragma unroll
    for (int j = 0; j < 4; j++) bn[j] = ((const float4*)(bias + n0))[j];

    #pragma unroll
    for (int p = 0; p < 4; p++) {
        int pp = pg * 4 + p;
        float4 acc[4];
        #pragma unroll
        for (int j = 0; j < 4; j++) acc[j] = bn[j];
        #pragma unroll
        for (int h = 0; h < HH; h++) {
            float d = dsm[h * 16 + pp];
            #pragma unroll
            for (int j = 0; j < 4; j++) {
                acc[j].x = fmaf(u[h][j].x, d, acc[j].x);
                acc[j].y = fmaf(u[h][j].y, d, acc[j].y);
                acc[j].z = fmaf(u[h][j].z, d, acc[j].z);
                acc[j].w = fmaf(u[h][j].w, d, acc[j].w);
            }
        }
        float4* yrow = (float4*)(Y + (((size_t)(b * PP + pt * 16 + pp)) << 10) + n0);
        #pragma unroll
        for (int j = 0; j < 4; j++) yrow[j] = acc[j];
    }
}

extern "C" void kernel_launch(void* const* d_in, const int* in_sizes, int n_in,
                              void* d_out, int out_size) {
    const float* Q    = (const float*)d_in[0];
    const float* K    = (const float*)d_in[1];
    const float* V    = (const float*)d_in[2];
    const float* W    = (const float*)d_in[3];
    const float* bias = (const float*)d_in[4];
    float* Y = (float*)d_out;

    k_reduce<<<8704, 256>>>(Q, K, V);
    k_mid<<<832, 256>>>(W);
    k_nodes<<<128, 256>>>();
    k_diag<<<128, 256>>>();
    k_out<<<512, 256>>>(bias, Y);
}

// round 16
// speedup vs baseline: 1.4400x; 1.4400x over previous
#include <cuda_runtime.h>

#define BB 4
#define PP 2048
#define EE 1024
#define HH 16
#define HD 64
#define NB2 64          // ks bins
#define NC 11           // Taylor coefs c0..c10
#define NPART 8
#define NVP 32
#define NNODE 512       // interpolation nodes per bh

// Scratch (fully overwritten every launch)
__device__ __align__(16) float g_Qs[BB*HH*PP];
__device__ __align__(16) float g_Ks[BB*HH*PP];
__device__ __align__(16) float g_Vpart[BB*NVP*EE];
__device__ __align__(16) float g_U[BB*HH*EE];       // [b][h][n]
__device__ __align__(16) float g_bt[BB*HH*NPART*NC*NB2];
__device__ __align__(16) float g_tab[BB*HH*NNODE];  // log2-denominator nodes
__device__ __align__(8)  float2 g_mnmx[BB*HH];      // ks min/max
__device__ __align__(16) float4 g_qmm[BB*HH];       // (amin2, h2, 1/h2, pad)

__device__ __forceinline__ float ex2f(float x){
    float y; asm("ex2.approx.ftz.f32 %0, %1;" : "=f"(y) : "f"(x)); return y;
}
__device__ __forceinline__ float lg2f(float x){
    float y; asm("lg2.approx.f32 %0, %1;" : "=f"(y) : "f"(x)); return y;
}

// ---------------------------------------------------------------------------
// K1: blocks [0,512): V partial column sums. [512,8704): Q/K head row-sums.
// ---------------------------------------------------------------------------
__global__ void k_reduce(const float* __restrict__ Q, const float* __restrict__ K,
                         const float* __restrict__ V) {
    int bid = blockIdx.x;
    int tid = threadIdx.x;
    if (bid < 512) {
        int b = bid >> 7, r = bid & 127, pc = r >> 2, cg = r & 3;
        int c = cg * 256 + tid;
        const float* base = V + ((size_t)b * PP + pc * 64) * EE + c;
        float s = 0.f;
        #pragma unroll 16
        for (int p = 0; p < 64; p++) s += base[(size_t)p * EE];
        g_Vpart[(b * NVP + pc) * EE + c] = s;
    } else {
        int base = bid - 512;
        const float* src; float* dst;
        if (base < 4096) { src = Q; dst = g_Qs; }
        else             { src = K; dst = g_Ks; base -= 4096; }
        int bh = base >> 6;
        int ptile = base & 63;
        int b = bh >> 4, h = bh & 15;
        int seg = tid >> 4, lane16 = tid & 15;
        int p0 = ptile * 32 + seg;
        const float4* r0 = (const float4*)(src + (((size_t)(b * PP + p0)) << 10) + h * HD);
        const float4* r1 = (const float4*)(src + (((size_t)(b * PP + p0 + 16)) << 10) + h * HD);
        float4 v0 = r0[lane16];
        float4 v1 = r1[lane16];
        float s0 = (v0.x + v0.y) + (v0.z + v0.w);
        float s1 = (v1.x + v1.y) + (v1.z + v1.w);
        #pragma unroll
        for (int off = 8; off; off >>= 1) {
            s0 += __shfl_down_sync(0xffffffffu, s0, off, 16);
            s1 += __shfl_down_sync(0xffffffffu, s1, off, 16);
        }
        __shared__ float sm[32];
        if (lane16 == 0) { sm[seg] = s0; sm[16 + seg] = s1; }
        __syncthreads();
        if (tid < 32) dst[(bh << 11) + ptile * 32 + tid] = sm[tid];
    }
}

// ---------------------------------------------------------------------------
// min/max of arr[2048], exact. 256 threads.
// ---------------------------------------------------------------------------
__device__ __forceinline__ void ks_minmax(const float4* kr4, int tid,
                                          float* s_mn, float* s_mx) {
    __shared__ float rmn[8], rmx[8];
    float mn = 3.4e38f, mx = -3.4e38f;
    #pragma unroll
    for (int i = 0; i < 2; i++) {
        float4 v = kr4[i * 256 + tid];
        mn = fminf(mn, fminf(fminf(v.x, v.y), fminf(v.z, v.w)));
        mx = fmaxf(mx, fmaxf(fmaxf(v.x, v.y), fmaxf(v.z, v.w)));
    }
    #pragma unroll
    for (int off = 16; off; off >>= 1) {
        mn = fminf(mn, __shfl_xor_sync(0xffffffffu, mn, off));
        mx = fmaxf(mx, __shfl_xor_sync(0xffffffffu, mx, off));
    }
    if ((tid & 31) == 0) { rmn[tid >> 5] = mn; rmx[tid >> 5] = mx; }
    __syncthreads();
    if (tid == 0) {
        float a = rmn[0], c = rmx[0];
        #pragma unroll
        for (int w = 1; w < 8; w++) { a = fminf(a, rmn[w]); c = fmaxf(c, rmx[w]); }
        *s_mn = a; *s_mx = c;
    }
    __syncthreads();
}

// ---------------------------------------------------------------------------
// K_mid: [0,512): ks bin tables. [512,768): proj_u. [768,832): Qs min/max.
// ---------------------------------------------------------------------------
__global__ void k_mid(const float* __restrict__ W) {
    int bid = blockIdx.x;
    int tid = threadIdx.x;
    if (bid < 512) {
        int bh = bid >> 3, part = bid & 7;
        __shared__ float s_mn, s_mx;
        __shared__ float tb[NC][NB2];
        const float4* kr4 = (const float4*)(g_Ks + ((size_t)bh << 11));
        ks_minmax(kr4, tid, &s_mn, &s_mx);
        for (int i = tid; i < NC * NB2; i += 256) ((float*)tb)[i] = 0.f;
        __syncthreads();

        float mn = s_mn, mx = s_mx;
        float w = fmaxf(mx - mn, 1e-20f) * (1.0f / NB2);
        float invw = 1.0f / w;

        float k = g_Ks[((size_t)bh << 11) + (part << 8) + tid];
        int idx = (int)((k - mn) * invw);
        idx = max(0, min(NB2 - 1, idx));
        float kb = mn + ((float)idx + 0.5f) * w;
        float d  = k - kb;
        float t = 1.0f;
        atomicAdd(&tb[0][idx], 1.0f);
        const float rc[10] = {1.f, 0.5f, 1.f/3.f, 0.25f, 0.2f, 1.f/6.f,
                              1.f/7.f, 0.125f, 1.f/9.f, 0.1f};
        #pragma unroll
        for (int c = 1; c <= 10; c++) {
            t *= d * rc[c - 1];
            atomicAdd(&tb[c][idx], t);
        }
        __syncthreads();

        float* out = g_bt + (size_t)((bh * NPART + part) * NC) * NB2;
        for (int i = tid; i < NC * NB2; i += 256) out[i] = ((float*)tb)[i];
        if (part == 0 && tid == 0) g_mnmx[bh] = make_float2(mn, mx);
    } else if (bid < 768) {
        int blk = bid - 512;
        int b = blk >> 6, h = (blk >> 2) & 15, nc = blk & 3;
        __shared__ float vs[HD];
        if (tid < HD) {
            float s = 0.f;
            #pragma unroll
            for (int pc = 0; pc < NVP; pc++)
                s += g_Vpart[(b * NVP + pc) * EE + h * HD + tid];
            vs[tid] = s;
        }
        __syncthreads();
        int n = nc * 256 + tid;
        const float4* wr = (const float4*)(W + (size_t)n * EE + h * HD);
        float acc = 0.f;
        #pragma unroll
        for (int e = 0; e < 16; e++) {
            float4 w4 = wr[e];
            acc += w4.x * vs[4*e] + w4.y * vs[4*e+1] + w4.z * vs[4*e+2] + w4.w * vs[4*e+3];
        }
        g_U[((b * HH + h) << 10) + n] = acc;
    } else {
        int bh = bid - 768;
        __shared__ float s_mn, s_mx;
        ks_minmax((const float4*)(g_Qs + ((size_t)bh << 11)), tid, &s_mn, &s_mx);
        if (tid == 0) {
            const float C2 = 0.125f * 1.44269504088896340736f;
            float amin2 = C2 * s_mn, amax2 = C2 * s_mx;
            if (amin2 > amax2) { float t2 = amin2; amin2 = amax2; amax2 = t2; }
            float h2 = fmaxf(amax2 - amin2, 1e-20f) * (1.0f / 507.0f);
            g_qmm[bh] = make_float4(amin2, h2, 1.0f / h2, 0.f);
        }
    }
}

// ---------------------------------------------------------------------------
// K_nodes: g(a2) = log2 sum_j 2^(a2*ks_j) at 512 nodes per bh.
//   grid 128 = 64bh x 2 halves; 256 threads = 1 node each.
// ---------------------------------------------------------------------------
__global__ void __launch_bounds__(256) k_nodes() {
    int bh = blockIdx.x >> 1, half = blockIdx.x & 1;
    int tid = threadIdx.x;
    __shared__ __align__(16) float cf[NB2][12];
    __shared__ float2 s_mm;
    __shared__ float4 s_qmm;
    if (tid == 0) { s_mm = g_mnmx[bh]; s_qmm = g_qmm[bh]; }

    {
        const float* bt = g_bt + (size_t)(bh * NPART * NC) * NB2;
        for (int i = tid; i < NC * NB2; i += 256) {
            int c = i >> 6, bin = i & 63;
            float s = 0.f;
            #pragma unroll
            for (int part = 0; part < NPART; part++)
                s += bt[(size_t)(part * NC) * NB2 + i];
            cf[bin][c] = s;
        }
        for (int i = tid; i < NB2; i += 256) cf[i][11] = 0.f;
    }
    __syncthreads();

    float mn = s_mm.x, mx = s_mm.y;
    float w = fmaxf(mx - mn, 1e-20f) * (1.0f / NB2);
    const float LN2 = 0.69314718055994530942f;

    int node = half * 256 + tid;
    float a2 = fmaf((float)(node - 2), s_qmm.y, s_qmm.x);
    float a  = a2 * LN2;
    float nM = -((a2 >= 0.f) ? a2 * mx : a2 * mn);
    float rd = ex2f(a2 * w);

    float acc0 = 0.f, acc1 = 0.f;
    #pragma unroll 1
    for (int seg = 0; seg < 4; seg++) {
        float kb = fmaf((float)(seg * 16) + 0.5f, w, mn);
        float e  = ex2f(fmaf(a2, kb, nM));
        float accs = 0.f;
        #pragma unroll
        for (int t = 0; t < 16; t++) {
            int bin = seg * 16 + t;
            float4 A = *(const float4*)&cf[bin][0];
            float4 B = *(const float4*)&cf[bin][4];
            float4 C = *(const float4*)&cf[bin][8];
            float p = C.z;
            p = fmaf(a, p, C.y);
            p = fmaf(a, p, C.x);
            p = fmaf(a, p, B.w);
            p = fmaf(a, p, B.z);
            p = fmaf(a, p, B.y);
            p = fmaf(a, p, B.x);
            p = fmaf(a, p, A.w);
            p = fmaf(a, p, A.z);
            p = fmaf(a, p, A.y);
            p = fmaf(a, p, A.x);
            accs = fmaf(e, p, accs);
            e *= rd;
        }
        if (seg & 1) acc1 += accs; else acc0 += accs;
    }
    float denom = acc0 + acc1;
    g_tab[(bh << 9) + node] = lg2f(denom) - nM;
}

// ---------------------------------------------------------------------------
// K4 (fused diag+out): per block (b, pt): load the 16 per-head node tables
//   (32KB smem), interpolate the 512 diag values for this 32-p tile in-block
//   (2 queries/thread), then the R14-proven GEMM: thread = 4 consecutive n,
//   u4[16] in regs (coalesced LDG.128), diag broadcast from smem.
//   grid 256 = 4b x 64pt; 256 threads.
// ---------------------------------------------------------------------------
__global__ void __launch_bounds__(256) k_out(const float* __restrict__ bias,
                                             float* __restrict__ Y) {
    int pt = blockIdx.x & 63;
    int b  = blockIdx.x >> 6;
    int tid = threadIdx.x;

    __shared__ __align__(16) float gt[HH][NNODE];   // 32 KB
    __shared__ float dsm[HH * 32];
    __shared__ __align__(16) float4 s_qmm[HH];

    if (tid < HH) s_qmm[tid] = g_qmm[b * HH + tid];
    // load 16 node tables: 2048 float4, 8 per thread
    #pragma unroll
    for (int r = 0; r < 8; r++) {
        int idx = r * 256 + tid;
        int h = idx >> 7, q = idx & 127;
        ((float4*)gt[h])[q] = ((const float4*)(g_tab + ((b * HH + h) << 9)))[q];
    }
    __syncthreads();

    // interpolate 512 diag values (2 per thread)
    const float C2 = 0.125f * 1.44269504088896340736f;
    #pragma unroll
    for (int r = 0; r < 2; r++) {
        int idx = r * 256 + tid;
        int h = idx >> 5, pl = idx & 31;
        int bh = b * HH + h;
        int i = pt * 32 + pl;
        float a2 = C2 * g_Qs[((size_t)bh << 11) + i];
        float ki = g_Ks[((size_t)bh << 11) + i];
        float4 qm = s_qmm[h];
        float x = fmaf(a2 - qm.x, qm.z, 2.0f);
        int i0 = (int)floorf(x);
        i0 = min(max(i0, 1), 509);
        float t = x - (float)i0;
        float g0 = gt[h][i0 - 1], g1 = gt[h][i0], g2 = gt[h][i0 + 1], g3 = gt[h][i0 + 2];
        float m1 = 0.5f * (g2 - g0);
        float m2 = 0.5f * (g3 - g1);
        float dg = g2 - g1;
        float c2v = 3.f * dg - 2.f * m1 - m2;
        float c3v = -2.f * dg + m1 + m2;
        float g = g1 + t * (m1 + t * (c2v + t * c3v));
        dsm[h * 32 + pl] = ex2f(fmaf(a2, ki, -g));
    }
    __syncthreads();

    int n0 = tid << 2;
    float4 u4[HH];
    #pragma unroll
    for (int h = 0; h < HH; h++)
        u4[h] = *(const float4*)(g_U + ((b * HH + h) << 10) + n0);
    float4 bn = *(const float4*)(bias + n0);

    float4* out = (float4*)(Y + (((size_t)(b * PP + pt * 32)) << 10) + n0);
    #pragma unroll 2
    for (int p = 0; p < 32; p++) {
        float4 acc = bn;
        #pragma unroll
        for (int h = 0; h < HH; h++) {
            float d = dsm[h * 32 + p];
            acc.x = fmaf(u4[h].x, d, acc.x);
            acc.y = fmaf(u4[h].y, d, acc.y);
            acc.z = fmaf(u4[h].z, d, acc.z);
            acc.w = fmaf(u4[h].w, d, acc.w);
        }
        out[(size_t)p << 8] = acc;
    }
}

extern "C" void kernel_launch(void* const* d_in, const int* in_sizes, int n_in,
                              void* d_out, int out_size) {
    const float* Q    = (const float*)d_in[0];
    const float* K    = (const float*)d_in[1];
    const float* V    = (const float*)d_in[2];
    const float* W    = (const float*)d_in[3];
    const float* bias = (const float*)d_in[4];
    float* Y = (float*)d_out;

    k_reduce<<<8704, 256>>>(Q, K, V);
    k_mid<<<832, 256>>>(W);
    k_nodes<<<128, 256>>>();
    k_out<<<256, 256>>>(bias, Y);
}